// round 15
// baseline (speedup 1.0000x reference)
#include <cuda_runtime.h>
#include <cuda_fp16.h>
#include <math.h>
#include <stdint.h>

#define C_DIM   1024
#define N_HEADS 16
#define HD      64
#define N_LAYERS 6
#define HID_DIM 4096
#define BATCH   2
#define SEQ     2048
#define NROWS   (BATCH*SEQ)
#define WIN     1000
#define NPERS   296     // 2 CTAs/SM x 148 SMs

// ================= scratch (no allocations allowed) =================
__device__ float g_x   [NROWS * C_DIM];
__device__ float g_tmp [NROWS * C_DIM];
__device__ __half g_xh[NROWS * C_DIM];
__device__ __half g_ah[NROWS * C_DIM];
__device__ __half g_hh[NROWS * HID_DIM];
__device__ __half g_qkvh[NROWS * 3 * C_DIM];
// per-layer fp16 weight buffers (dedicated per matrix)
__device__ __half g_wq[3 * C_DIM * C_DIM];
__device__ __half g_wo[C_DIM * C_DIM];
__device__ __half g_w1[HID_DIM * C_DIM];
__device__ __half g_w2[C_DIM * HID_DIM];

// ================= helpers =================
__device__ __forceinline__ uint32_t smem_to_u32(const void* p) {
    uint32_t a;
    asm("{ .reg .u64 t; cvta.to.shared.u64 t, %1; cvt.u32.u64 %0, t; }" : "=r"(a) : "l"(p));
    return a;
}

__device__ __forceinline__ void ldsm4(uint32_t* r, uint32_t addr) {
    asm volatile("ldmatrix.sync.aligned.m8n8.x4.shared.b16 {%0,%1,%2,%3}, [%4];"
                 : "=r"(r[0]), "=r"(r[1]), "=r"(r[2]), "=r"(r[3]) : "r"(addr));
}
__device__ __forceinline__ void ldsm4t(uint32_t* r, uint32_t addr) {
    asm volatile("ldmatrix.sync.aligned.m8n8.x4.trans.shared.b16 {%0,%1,%2,%3}, [%4];"
                 : "=r"(r[0]), "=r"(r[1]), "=r"(r[2]), "=r"(r[3]) : "r"(addr));
}
__device__ __forceinline__ void mma16816(float* d, const uint32_t* a, uint32_t b0, uint32_t b1) {
    asm volatile("mma.sync.aligned.m16n8k16.row.col.f32.f16.f16.f32 "
                 "{%0,%1,%2,%3}, {%4,%5,%6,%7}, {%8,%9}, {%0,%1,%2,%3};"
                 : "+f"(d[0]), "+f"(d[1]), "+f"(d[2]), "+f"(d[3])
                 : "r"(a[0]), "r"(a[1]), "r"(a[2]), "r"(a[3]), "r"(b0), "r"(b1));
}
__device__ __forceinline__ uint32_t packh(float lo, float hi) {
    uint32_t r;
    asm("cvt.rn.f16x2.f32 %0, %1, %2;" : "=r"(r) : "f"(hi), "f"(lo));
    return r;
}
#define CPA16(dst, src) \
    asm volatile("cp.async.cg.shared.global [%0], [%1], 16;" :: "r"(dst), "l"(src))

// ================= 4-way weight cast kernel (fp32 -> fp16) =================
__global__ void cast4_kernel(
    const float* __restrict__ s0, __half* __restrict__ d0, int n0,
    const float* __restrict__ s1, __half* __restrict__ d1, int n1,
    const float* __restrict__ s2, __half* __restrict__ d2, int n2,
    const float* __restrict__ s3, __half* __restrict__ d3, int n3)
{
    int total = (n0 + n1 + n2 + n3) >> 1;
    for (int i = blockIdx.x * blockDim.x + threadIdx.x; i < total;
         i += gridDim.x * blockDim.x) {
        int j = i << 1;
        const float* s; __half* d;
        if (j < n0)              { s = s0; d = d0; }
        else if ((j -= n0) < n1) { s = s1; d = d1; }
        else if ((j -= n1) < n2) { s = s2; d = d2; }
        else                     { j -= n2; s = s3; d = d3; }
        float2 v = *(const float2*)(s + j);
        *(__half2*)(d + j) = __floats2half2_rn(v.x, v.y);
    }
}

// ================= block reduce =================
__device__ __forceinline__ float blk_sum(float v, float* sh) {
    int tid = threadIdx.x;
    sh[tid] = v; __syncthreads();
#pragma unroll
    for (int s = 128; s > 0; s >>= 1) { if (tid < s) sh[tid] += sh[tid + s]; __syncthreads(); }
    float r = sh[0]; __syncthreads();
    return r;
}

// ================= input LN + positional embedding =================
__global__ __launch_bounds__(256) void embed_ln_kernel(
    const float* __restrict__ x, const float* __restrict__ g, const float* __restrict__ b,
    float* __restrict__ out, __half* __restrict__ oh)
{
    __shared__ float sh[256];
    int r = blockIdx.x, t = r % SEQ, tid = threadIdx.x;
    const float* xr = x + (size_t)r * C_DIM;
    float v[4]; float s = 0.f;
#pragma unroll
    for (int i = 0; i < 4; i++) { v[i] = xr[tid + 256 * i]; s += v[i]; }
    float mean = blk_sum(s, sh) * (1.0f / C_DIM);
    float d2 = 0.f;
#pragma unroll
    for (int i = 0; i < 4; i++) { float d = v[i] - mean; d2 += d * d; }
    float inv = rsqrtf(blk_sum(d2, sh) * (1.0f / C_DIM) + 1e-5f);
    const float kln = 9.2103403719761836f / 511.0f;
    float tf = (float)t;
#pragma unroll
    for (int i = 0; i < 4; i++) {
        int c = tid + 256 * i;
        float ph = (c < 512) ? tf * expf(-((float)c) * kln) : tf * expf(-((float)(c - 512)) * kln);
        float pos = (c < 512) ? cosf(ph) : sinf(ph);
        float y = (v[i] - mean) * inv * g[c] + b[c] + pos;
        size_t idx = (size_t)r * C_DIM + c;
        out[idx] = y;
        oh[idx] = __float2half_rn(y);
    }
}

// ================= y = LN(xin+add) =================
template<int SPLIT>
__global__ __launch_bounds__(256) void add_ln_kernel(
    const float* __restrict__ xin, const float* __restrict__ add,
    const float* __restrict__ g, const float* __restrict__ b,
    float* __restrict__ out, __half* __restrict__ oh)
{
    __shared__ float sh[256];
    int r = blockIdx.x, tid = threadIdx.x;
    const float* xr = xin + (size_t)r * C_DIM;
    const float* ar = add + (size_t)r * C_DIM;
    float v[4]; float s = 0.f;
#pragma unroll
    for (int i = 0; i < 4; i++) { int c = tid + 256 * i; v[i] = xr[c] + ar[c]; s += v[i]; }
    float mean = blk_sum(s, sh) * (1.0f / C_DIM);
    float d2 = 0.f;
#pragma unroll
    for (int i = 0; i < 4; i++) { float d = v[i] - mean; d2 += d * d; }
    float inv = rsqrtf(blk_sum(d2, sh) * (1.0f / C_DIM) + 1e-5f);
#pragma unroll
    for (int i = 0; i < 4; i++) {
        int c = tid + 256 * i;
        float y = (v[i] - mean) * inv * g[c] + b[c];
        size_t idx = (size_t)r * C_DIM + c;
        out[idx] = y;
        if (SPLIT) oh[idx] = __float2half_rn(y);
    }
}

// ================= fp16 1-pass HMMA GEMM, persistent CTAs ===================
// C[M,N] = A[M,K] * B[N,K]^T + bias (fp16 in, fp32 accum)
// CTA tile 128x128, 256 thr (8 warps 2Mx4N, warp 64x32), BK=64,
// 3-stage cp.async (32KB/stage), 2 CTAs/SM, tile-stride loop (no wave tail).
// OUT_MODE 0: fp32 + bias. 1: gelu(.)->fp16. 2: (.)*qscale->fp16 (QKV).
#define GEMM_SMEM_BYTES (1024 + 3 * 32768)

template<int OUT_MODE>
__global__ __launch_bounds__(256, 2) void gemm_hmma1(
    const __half* __restrict__ Ah, const __half* __restrict__ Bh,
    const float* __restrict__ bias,
    float* __restrict__ Cf, __half* __restrict__ Ch,
    int M, int N, int K)
{
    extern __shared__ char dsm[];
    const uint32_t smbase = (smem_to_u32(dsm) + 1023u) & ~1023u;
    const int tid = threadIdx.x;
    const int wid = tid >> 5;
    const int lid = tid & 31;
    const int warp_m = wid & 1;
    const int warp_n = wid >> 1;
    const int nchunk = K >> 6;
    const int ntx = N >> 7;
    const int ntiles = ntx * (M >> 7);
    const size_t rowbytes = (size_t)K * 2;

    const int lane15 = lid & 15;
    const int lanehi = lid >> 4;
    const int xr = lane15 & 7;
    const int lr = lid >> 2;
    const int lc = (lid & 3) * 2;

    for (int tile = blockIdx.x; tile < ntiles; tile += gridDim.x) {
        const int row0 = (tile / ntx) << 7;
        const int col0 = (tile % ntx) << 7;
        const char* gsrc[2] = {
            (const char*)(Ah + (size_t)row0 * K),
            (const char*)(Bh + (size_t)col0 * K) };

        auto load_chunk = [&](int c, int st) {
            const uint32_t sb = smbase + st * 32768;
            const size_t koff = (size_t)c * 128;
#pragma unroll
            for (int t = 0; t < 2; t++) {
#pragma unroll
                for (int j = 0; j < 4; j++) {
                    int u = tid + j * 256;             // 0..1023
                    int r = u >> 3;
                    int cb = (u & 7) * 16;
                    const char* g = gsrc[t] + (size_t)r * rowbytes + koff + cb;
                    uint32_t sa = sb + t * 16384 + (uint32_t)(r * 128 + (cb ^ ((r & 7) << 4)));
                    CPA16(sa, g);
                }
            }
            asm volatile("cp.async.commit_group;");
        };

        float acc[4][4][4];
#pragma unroll
        for (int a = 0; a < 4; a++)
#pragma unroll
            for (int b = 0; b < 4; b++)
#pragma unroll
                for (int i = 0; i < 4; i++) acc[a][b][i] = 0.f;

        load_chunk(0, 0);
        load_chunk(1, 1);

        for (int c = 0; c < nchunk; c++) {
            if (c + 1 < nchunk) {
                asm volatile("cp.async.wait_group 1;");
            } else {
                asm volatile("cp.async.wait_group 0;");
            }
            __syncthreads();
            if (c + 2 < nchunk) load_chunk(c + 2, (c + 2) % 3);

            const uint32_t sb = smbase + (c % 3) * 32768;
            const uint32_t aBase = sb          + (uint32_t)(warp_m * 64 + lane15) * 128;
            const uint32_t bBase = sb + 16384  + (uint32_t)(warp_n * 32 + lane15) * 128;

#pragma unroll
            for (int ks = 0; ks < 4; ks++) {
                const uint32_t uoff = (uint32_t)(((ks * 2 + lanehi) ^ xr) * 16);
                uint32_t ah[4][4], bhv[2][4];
#pragma unroll
                for (int mt = 0; mt < 4; mt++)
                    ldsm4(ah[mt], aBase + mt * 2048 + uoff);
#pragma unroll
                for (int pt = 0; pt < 2; pt++)
                    ldsm4(bhv[pt], bBase + pt * 2048 + uoff);
#pragma unroll
                for (int mt = 0; mt < 4; mt++) {
#pragma unroll
                    for (int nt = 0; nt < 4; nt++) {
                        const int pt = nt >> 1, o = nt & 1;
                        mma16816(acc[mt][nt], ah[mt], bhv[pt][o], bhv[pt][o + 2]);
                    }
                }
            }
            __syncthreads();
        }

        // epilogue
#pragma unroll
        for (int mt = 0; mt < 4; mt++) {
            const int row = row0 + warp_m * 64 + mt * 16 + lr;
#pragma unroll
            for (int nt = 0; nt < 4; nt++) {
                const int col = col0 + warp_n * 32 + nt * 8 + lc;
                const float b0 = bias[col], b1 = bias[col + 1];
                float v0 = acc[mt][nt][0] + b0, v1 = acc[mt][nt][1] + b1;
                float v2 = acc[mt][nt][2] + b0, v3 = acc[mt][nt][3] + b1;
                if (OUT_MODE == 0) {
                    float2 w0; w0.x = v0; w0.y = v1;
                    float2 w1; w1.x = v2; w1.y = v3;
                    *(float2*)(Cf + (size_t)row * N + col) = w0;
                    *(float2*)(Cf + (size_t)(row + 8) * N + col) = w1;
                } else {
                    if (OUT_MODE == 1) {
                        v0 = 0.5f * v0 * (1.f + erff(v0 * 0.70710678118654752f));
                        v1 = 0.5f * v1 * (1.f + erff(v1 * 0.70710678118654752f));
                        v2 = 0.5f * v2 * (1.f + erff(v2 * 0.70710678118654752f));
                        v3 = 0.5f * v3 * (1.f + erff(v3 * 0.70710678118654752f));
                    } else {
                        float sc = (col < C_DIM) ? 0.125f : 1.0f;  // scale Q only
                        v0 *= sc; v1 *= sc; v2 *= sc; v3 *= sc;
                    }
                    __half2 hh0 = __floats2half2_rn(v0, v1);
                    __half2 hh1 = __floats2half2_rn(v2, v3);
                    *(__half2*)(Ch + (size_t)row * N + col) = hh0;
                    *(__half2*)(Ch + (size_t)(row + 8) * N + col) = hh1;
                }
            }
        }
    }
}

// ================= fp16 HMMA flash attention (sliding window) ===================
// Pure fp16: S = Q*K^T (1 pass), P fp16, O += P*V (1 pass).
#define ATTN_SMEM (1024 + 3 * 8192)

__global__ __launch_bounds__(128, 4) void attn_mma_kernel(
    const __half* __restrict__ qkvh,
    const float* __restrict__ bqkv_l,
    __half* __restrict__ oh)
{
    extern __shared__ char dsm[];
    const uint32_t base = (smem_to_u32(dsm) + 1023u) & ~1023u;
    const uint32_t sQ = base;
    const uint32_t sK = base + 8192;
    const uint32_t sV = base + 16384;

    const int tid = threadIdx.x, wid = tid >> 5, lid = tid & 31;
    const int b = blockIdx.z, h = blockIdx.y, q0 = blockIdx.x * 64;
    const int lane15 = lid & 15, lanehi = lid >> 4, xr = lane15 & 7;
    const int tig = lid & 3, gid = lid >> 2;
    const size_t RS = 3 * C_DIM;

    // ---- Q tile: 64 rows x 128B ----
#pragma unroll
    for (int i = 0; i < 4; i++) {
        int u = tid + i * 128;          // 0..511
        int r = u >> 3, cu = u & 7;
        const char* g = (const char*)(qkvh + (size_t)(b * SEQ + q0 + r) * RS + h * HD) + cu * 16;
        CPA16(sQ + (uint32_t)(r * 128 + ((cu ^ (r & 7)) * 16)), g);
    }
    asm volatile("cp.async.commit_group;");
    asm volatile("cp.async.wait_group 0;");
    __syncthreads();

    uint32_t qf[4][4];
    {
        const uint32_t qrb = (uint32_t)((wid * 16 + lane15) * 128);
#pragma unroll
        for (int ks = 0; ks < 4; ks++) {
            const uint32_t uoff = (uint32_t)(((ks * 2 + lanehi) ^ xr) * 16);
            ldsm4(qf[ks], sQ + qrb + uoff);
        }
    }

    // ---- past zero-token init ----
    const int tq0 = q0 + wid * 16 + gid, tq1 = tq0 + 8;
    const float* bk = bqkv_l + C_DIM + h * HD;
    const float* bv = bqkv_l + 2 * C_DIM + h * HD;
    float sp0 = 0.f, sp1 = 0.f;
    {
        const __half* q0p = qkvh + (size_t)(b * SEQ + tq0) * RS + h * HD + tig * 16;
        const __half* q1p = qkvh + (size_t)(b * SEQ + tq1) * RS + h * HD + tig * 16;
#pragma unroll
        for (int dd = 0; dd < 16; dd++) {
            float w = bk[tig * 16 + dd];
            sp0 += __half2float(q0p[dd]) * w;
            sp1 += __half2float(q1p[dd]) * w;
        }
        sp0 += __shfl_xor_sync(0xFFFFFFFF, sp0, 1); sp0 += __shfl_xor_sync(0xFFFFFFFF, sp0, 2);
        sp1 += __shfl_xor_sync(0xFFFFFFFF, sp1, 1); sp1 += __shfl_xor_sync(0xFFFFFFFF, sp1, 2);
    }
    const bool pv0 = (tq0 <= WIN - 1), pv1 = (tq1 <= WIN - 1);
    float m0 = pv0 ? sp0 : -1e30f, m1 = pv1 ? sp1 : -1e30f;
    float l0 = pv0 ? 1.f : 0.f,     l1 = pv1 ? 1.f : 0.f;
    float o[8][4];
#pragma unroll
    for (int nt = 0; nt < 8; nt++) {
        float bva = bv[nt * 8 + 2 * tig], bvb = bv[nt * 8 + 2 * tig + 1];
        o[nt][0] = pv0 ? bva : 0.f; o[nt][1] = pv0 ? bvb : 0.f;
        o[nt][2] = pv1 ? bva : 0.f; o[nt][3] = pv1 ? bvb : 0.f;
    }

    // ---- main loop over 64-key tiles ----
    const int jlo = (q0 > WIN) ? ((q0 - WIN) & ~63) : 0;
    for (int j0 = jlo; j0 < q0 + 64; j0 += 64) {
        __syncthreads();
#pragma unroll
        for (int i = 0; i < 8; i++) {
            int u = tid + i * 128;       // 0..1023
            int t = u >> 9, idx = u & 511;
            int r = idx >> 3, cu = idx & 7;
            const size_t coloff = (size_t)C_DIM * (1 + t) + h * HD;
            const char* g = (const char*)(qkvh + (size_t)(b * SEQ + j0 + r) * RS + coloff) + cu * 16;
            CPA16(sK + (uint32_t)(t * 8192 + r * 128 + ((cu ^ (r & 7)) * 16)), g);
        }
        asm volatile("cp.async.commit_group;");
        asm volatile("cp.async.wait_group 0;");
        __syncthreads();

        // S = Q.K^T
        float s[8][4];
#pragma unroll
        for (int nt = 0; nt < 8; nt++)
#pragma unroll
            for (int i = 0; i < 4; i++) s[nt][i] = 0.f;
#pragma unroll
        for (int ks = 0; ks < 4; ks++) {
            const uint32_t uoff = (uint32_t)(((ks * 2 + lanehi) ^ xr) * 16);
            uint32_t kf[4][4];
#pragma unroll
            for (int pt = 0; pt < 4; pt++)
                ldsm4(kf[pt], sK + (uint32_t)((pt * 16 + lane15) * 128) + uoff);
#pragma unroll
            for (int nt = 0; nt < 8; nt++) {
                const int pt = nt >> 1, oo = nt & 1;
                mma16816(s[nt], qf[ks], kf[pt][oo], kf[pt][oo + 2]);
            }
        }
        // mask
#pragma unroll
        for (int nt = 0; nt < 8; nt++)
#pragma unroll
            for (int i = 0; i < 4; i++) {
                int key = j0 + nt * 8 + 2 * tig + (i & 1);
                int tq = (i < 2) ? tq0 : tq1;
                int dlt = tq - key;
                if (dlt < 0 || dlt > WIN) s[nt][i] = -3.0e38f;
            }
        // online softmax
        float mc0 = -3.0e38f, mc1 = -3.0e38f;
#pragma unroll
        for (int nt = 0; nt < 8; nt++) {
            mc0 = fmaxf(mc0, fmaxf(s[nt][0], s[nt][1]));
            mc1 = fmaxf(mc1, fmaxf(s[nt][2], s[nt][3]));
        }
        mc0 = fmaxf(mc0, __shfl_xor_sync(0xFFFFFFFF, mc0, 1));
        mc0 = fmaxf(mc0, __shfl_xor_sync(0xFFFFFFFF, mc0, 2));
        mc1 = fmaxf(mc1, __shfl_xor_sync(0xFFFFFFFF, mc1, 1));
        mc1 = fmaxf(mc1, __shfl_xor_sync(0xFFFFFFFF, mc1, 2));
        float mn0 = fmaxf(m0, mc0), mn1 = fmaxf(m1, mc1);
        float a0 = __expf(m0 - mn0), a1 = __expf(m1 - mn1);
        float rs0 = 0.f, rs1 = 0.f;
#pragma unroll
        for (int nt = 0; nt < 8; nt++) {
            s[nt][0] = __expf(s[nt][0] - mn0); rs0 += s[nt][0];
            s[nt][1] = __expf(s[nt][1] - mn0); rs0 += s[nt][1];
            s[nt][2] = __expf(s[nt][2] - mn1); rs1 += s[nt][2];
            s[nt][3] = __expf(s[nt][3] - mn1); rs1 += s[nt][3];
        }
        rs0 += __shfl_xor_sync(0xFFFFFFFF, rs0, 1); rs0 += __shfl_xor_sync(0xFFFFFFFF, rs0, 2);
        rs1 += __shfl_xor_sync(0xFFFFFFFF, rs1, 1); rs1 += __shfl_xor_sync(0xFFFFFFFF, rs1, 2);
        l0 = l0 * a0 + rs0; l1 = l1 * a1 + rs1;
        m0 = mn0; m1 = mn1;
#pragma unroll
        for (int nt = 0; nt < 8; nt++) {
            o[nt][0] *= a0; o[nt][1] *= a0; o[nt][2] *= a1; o[nt][3] *= a1;
        }
        // pack P -> fp16 A-frags
        uint32_t pa[4][4];
#pragma unroll
        for (int kt = 0; kt < 4; kt++) {
            pa[kt][0] = packh(s[2 * kt][0],     s[2 * kt][1]);
            pa[kt][1] = packh(s[2 * kt][2],     s[2 * kt][3]);
            pa[kt][2] = packh(s[2 * kt + 1][0], s[2 * kt + 1][1]);
            pa[kt][3] = packh(s[2 * kt + 1][2], s[2 * kt + 1][3]);
        }
        // O += P * V
#pragma unroll
        for (int kt = 0; kt < 4; kt++) {
            const uint32_t vrb = (uint32_t)((kt * 16 + lane15) * 128);
            uint32_t vf[4][4];
#pragma unroll
            for (int j = 0; j < 4; j++) {
                const uint32_t uo = (uint32_t)(((j * 2 + lanehi) ^ xr) * 16);
                ldsm4t(vf[j], sV + vrb + uo);
            }
#pragma unroll
            for (int j = 0; j < 4; j++) {
                mma16816(o[2 * j],     pa[kt], vf[j][0], vf[j][1]);
                mma16816(o[2 * j + 1], pa[kt], vf[j][2], vf[j][3]);
            }
        }
    }

    const float r0 = 1.f / l0, r1 = 1.f / l1;
#pragma unroll
    for (int nt = 0; nt < 8; nt++) {
        const int col = h * HD + nt * 8 + 2 * tig;
        __half2 hh0 = __floats2half2_rn(o[nt][0] * r0, o[nt][1] * r0);
        __half2 hh1 = __floats2half2_rn(o[nt][2] * r1, o[nt][3] * r1);
        *(__half2*)(oh + (size_t)(b * SEQ + tq0) * C_DIM + col) = hh0;
        *(__half2*)(oh + (size_t)(b * SEQ + tq1) * C_DIM + col) = hh1;
    }
}

// ================= launcher =================
extern "C" void kernel_launch(void* const* d_in, const int* in_sizes, int n_in,
                              void* d_out, int out_size)
{
    const float* x      = (const float*)d_in[0];
    const float* norm_g = (const float*)d_in[1];
    const float* norm_b = (const float*)d_in[2];
    const float* Wqkv   = (const float*)d_in[3];
    const float* bqkv   = (const float*)d_in[4];
    const float* Wo     = (const float*)d_in[5];
    const float* bo     = (const float*)d_in[6];
    const float* ln1_g  = (const float*)d_in[7];
    const float* ln1_b  = (const float*)d_in[8];
    const float* ln2_g  = (const float*)d_in[9];
    const float* ln2_b  = (const float*)d_in[10];
    const float* W1     = (const float*)d_in[11];
    const float* b1     = (const float*)d_in[12];
    const float* W2     = (const float*)d_in[13];
    const float* b2     = (const float*)d_in[14];
    float* out = (float*)d_out;

    float *gx, *gtmp;
    __half *gxh, *gah, *ghh, *gqh, *gwq, *gwo, *gw1, *gw2;
    cudaGetSymbolAddress((void**)&gx,   g_x);
    cudaGetSymbolAddress((void**)&gtmp, g_tmp);
    cudaGetSymbolAddress((void**)&gxh,  g_xh);
    cudaGetSymbolAddress((void**)&gah,  g_ah);
    cudaGetSymbolAddress((void**)&ghh,  g_hh);
    cudaGetSymbolAddress((void**)&gqh,  g_qkvh);
    cudaGetSymbolAddress((void**)&gwq,  g_wq);
    cudaGetSymbolAddress((void**)&gwo,  g_wo);
    cudaGetSymbolAddress((void**)&gw1,  g_w1);
    cudaGetSymbolAddress((void**)&gw2,  g_w2);

    cudaFuncSetAttribute(gemm_hmma1<0>, cudaFuncAttributeMaxDynamicSharedMemorySize, GEMM_SMEM_BYTES);
    cudaFuncSetAttribute(gemm_hmma1<1>, cudaFuncAttributeMaxDynamicSharedMemorySize, GEMM_SMEM_BYTES);
    cudaFuncSetAttribute(gemm_hmma1<2>, cudaFuncAttributeMaxDynamicSharedMemorySize, GEMM_SMEM_BYTES);
    cudaFuncSetAttribute(attn_mma_kernel, cudaFuncAttributeMaxDynamicSharedMemorySize, ATTN_SMEM);

    const int NQ = 3 * C_DIM * C_DIM;   // 3M
    const int NO = C_DIM * C_DIM;       // 1M
    const int N1 = HID_DIM * C_DIM;     // 4M
    const int N2 = C_DIM * HID_DIM;     // 4M

    auto gemm_grid = [](int M, int N) {
        int tiles = (M >> 7) * (N >> 7);
        return (tiles < NPERS) ? tiles : NPERS;
    };

    embed_ln_kernel<<<NROWS, 256>>>(x, norm_g, norm_b, gx, gxh);

    for (int l = 0; l < N_LAYERS; l++) {
        const float* bqkv_l = bqkv + (size_t)l * 3 * C_DIM;

        // cast all 4 weight matrices in one launch (keeps attn at ncu launch #4)
        cast4_kernel<<<1184, 256>>>(
            Wqkv + (size_t)l * NQ, gwq, NQ,
            Wo   + (size_t)l * NO, gwo, NO,
            W1   + (size_t)l * N1, gw1, N1,
            W2   + (size_t)l * N2, gw2, N2);

        // qkv = (x @ Wqkv^T + bqkv), Q scaled by 1/8, fp16 out
        gemm_hmma1<2><<<gemm_grid(NROWS, 3 * C_DIM), 256, GEMM_SMEM_BYTES>>>(
            gxh, gwq, bqkv_l, nullptr, gqh,
            NROWS, 3 * C_DIM, C_DIM);

        // pure-fp16 HMMA flash attention (ncu launch #4 on layer 0)
        attn_mma_kernel<<<dim3(SEQ / 64, N_HEADS, BATCH), 128, ATTN_SMEM>>>(
            gqh, bqkv_l, gah);

        // o = attn @ Wo^T + bo
        gemm_hmma1<0><<<gemm_grid(NROWS, C_DIM), 256, GEMM_SMEM_BYTES>>>(
            gah, gwo, bo + (size_t)l * C_DIM, gtmp, nullptr,
            NROWS, C_DIM, C_DIM);

        // x = LN(x + o; ln1)
        add_ln_kernel<1><<<NROWS, 256>>>(gx, gtmp, ln1_g + l * C_DIM, ln1_b + l * C_DIM, gx, gxh);

        // hid = gelu(x @ W1^T + b1) -> fp16
        gemm_hmma1<1><<<gemm_grid(NROWS, HID_DIM), 256, GEMM_SMEM_BYTES>>>(
            gxh, gw1, b1 + (size_t)l * HID_DIM, nullptr, ghh,
            NROWS, HID_DIM, C_DIM);

        // ff = hid @ W2^T + b2
        gemm_hmma1<0><<<gemm_grid(NROWS, C_DIM), 256, GEMM_SMEM_BYTES>>>(
            ghh, gw2, b2 + (size_t)l * C_DIM, gtmp, nullptr,
            NROWS, C_DIM, HID_DIM);

        // x = LN(x + ff; ln2)
        if (l == N_LAYERS - 1)
            add_ln_kernel<0><<<NROWS, 256>>>(gx, gtmp, ln2_g + l * C_DIM, ln2_b + l * C_DIM, out, nullptr);
        else
            add_ln_kernel<1><<<NROWS, 256>>>(gx, gtmp, ln2_g + l * C_DIM, ln2_b + l * C_DIM, gx, gxh);
    }
}

// round 16
// speedup vs baseline: 1.0057x; 1.0057x over previous
#include <cuda_runtime.h>
#include <cuda_fp16.h>
#include <math.h>
#include <stdint.h>

#define C_DIM   1024
#define N_HEADS 16
#define HD      64
#define N_LAYERS 6
#define HID_DIM 4096
#define BATCH   2
#define SEQ     2048
#define NROWS   (BATCH*SEQ)
#define WIN     1000
#define NPERS   296     // 2 CTAs/SM x 148 SMs
// Q pre-scale: (1/sqrt(64)) * log2(e) -> softmax runs in log2 domain
#define QSCALE  0.18033688011112042f

// ================= scratch (no allocations allowed) =================
__device__ float g_x   [NROWS * C_DIM];
__device__ float g_tmp [NROWS * C_DIM];
__device__ __half g_xh[NROWS * C_DIM];
__device__ __half g_ah[NROWS * C_DIM];
__device__ __half g_hh[NROWS * HID_DIM];
__device__ __half g_qkvh[NROWS * 3 * C_DIM];
// per-layer fp16 weight buffers (dedicated per matrix)
__device__ __half g_wq[3 * C_DIM * C_DIM];
__device__ __half g_wo[C_DIM * C_DIM];
__device__ __half g_w1[HID_DIM * C_DIM];
__device__ __half g_w2[C_DIM * HID_DIM];

// ================= helpers =================
__device__ __forceinline__ uint32_t smem_to_u32(const void* p) {
    uint32_t a;
    asm("{ .reg .u64 t; cvta.to.shared.u64 t, %1; cvt.u32.u64 %0, t; }" : "=r"(a) : "l"(p));
    return a;
}
__device__ __forceinline__ float ex2f(float x) {
    float r;
    asm("ex2.approx.ftz.f32 %0, %1;" : "=f"(r) : "f"(x));
    return r;
}
__device__ __forceinline__ void ldsm4(uint32_t* r, uint32_t addr) {
    asm volatile("ldmatrix.sync.aligned.m8n8.x4.shared.b16 {%0,%1,%2,%3}, [%4];"
                 : "=r"(r[0]), "=r"(r[1]), "=r"(r[2]), "=r"(r[3]) : "r"(addr));
}
__device__ __forceinline__ void ldsm4t(uint32_t* r, uint32_t addr) {
    asm volatile("ldmatrix.sync.aligned.m8n8.x4.trans.shared.b16 {%0,%1,%2,%3}, [%4];"
                 : "=r"(r[0]), "=r"(r[1]), "=r"(r[2]), "=r"(r[3]) : "r"(addr));
}
__device__ __forceinline__ void mma16816(float* d, const uint32_t* a, uint32_t b0, uint32_t b1) {
    asm volatile("mma.sync.aligned.m16n8k16.row.col.f32.f16.f16.f32 "
                 "{%0,%1,%2,%3}, {%4,%5,%6,%7}, {%8,%9}, {%0,%1,%2,%3};"
                 : "+f"(d[0]), "+f"(d[1]), "+f"(d[2]), "+f"(d[3])
                 : "r"(a[0]), "r"(a[1]), "r"(a[2]), "r"(a[3]), "r"(b0), "r"(b1));
}
__device__ __forceinline__ uint32_t packh(float lo, float hi) {
    uint32_t r;
    asm("cvt.rn.f16x2.f32 %0, %1, %2;" : "=r"(r) : "f"(hi), "f"(lo));
    return r;
}
#define CPA16(dst, src) \
    asm volatile("cp.async.cg.shared.global [%0], [%1], 16;" :: "r"(dst), "l"(src))

// ================= 4-way weight cast kernel (fp32 -> fp16) =================
__global__ void cast4_kernel(
    const float* __restrict__ s0, __half* __restrict__ d0, int n0,
    const float* __restrict__ s1, __half* __restrict__ d1, int n1,
    const float* __restrict__ s2, __half* __restrict__ d2, int n2,
    const float* __restrict__ s3, __half* __restrict__ d3, int n3)
{
    int total = (n0 + n1 + n2 + n3) >> 1;
    for (int i = blockIdx.x * blockDim.x + threadIdx.x; i < total;
         i += gridDim.x * blockDim.x) {
        int j = i << 1;
        const float* s; __half* d;
        if (j < n0)              { s = s0; d = d0; }
        else if ((j -= n0) < n1) { s = s1; d = d1; }
        else if ((j -= n1) < n2) { s = s2; d = d2; }
        else                     { j -= n2; s = s3; d = d3; }
        float2 v = *(const float2*)(s + j);
        *(__half2*)(d + j) = __floats2half2_rn(v.x, v.y);
    }
}

// ================= block reduce =================
__device__ __forceinline__ float blk_sum(float v, float* sh) {
    int tid = threadIdx.x;
    sh[tid] = v; __syncthreads();
#pragma unroll
    for (int s = 128; s > 0; s >>= 1) { if (tid < s) sh[tid] += sh[tid + s]; __syncthreads(); }
    float r = sh[0]; __syncthreads();
    return r;
}

// ================= input LN + positional embedding =================
__global__ __launch_bounds__(256) void embed_ln_kernel(
    const float* __restrict__ x, const float* __restrict__ g, const float* __restrict__ b,
    float* __restrict__ out, __half* __restrict__ oh)
{
    __shared__ float sh[256];
    int r = blockIdx.x, t = r % SEQ, tid = threadIdx.x;
    const float* xr = x + (size_t)r * C_DIM;
    float v[4]; float s = 0.f;
#pragma unroll
    for (int i = 0; i < 4; i++) { v[i] = xr[tid + 256 * i]; s += v[i]; }
    float mean = blk_sum(s, sh) * (1.0f / C_DIM);
    float d2 = 0.f;
#pragma unroll
    for (int i = 0; i < 4; i++) { float d = v[i] - mean; d2 += d * d; }
    float inv = rsqrtf(blk_sum(d2, sh) * (1.0f / C_DIM) + 1e-5f);
    const float kln = 9.2103403719761836f / 511.0f;
    float tf = (float)t;
#pragma unroll
    for (int i = 0; i < 4; i++) {
        int c = tid + 256 * i;
        float ph = (c < 512) ? tf * expf(-((float)c) * kln) : tf * expf(-((float)(c - 512)) * kln);
        float pos = (c < 512) ? cosf(ph) : sinf(ph);
        float y = (v[i] - mean) * inv * g[c] + b[c] + pos;
        size_t idx = (size_t)r * C_DIM + c;
        out[idx] = y;
        oh[idx] = __float2half_rn(y);
    }
}

// ================= y = LN(in) (residual pre-added by GEMM epilogue) =========
template<int SPLIT>
__global__ __launch_bounds__(256) void ln_kernel(
    const float* __restrict__ xin,
    const float* __restrict__ g, const float* __restrict__ b,
    float* __restrict__ out, __half* __restrict__ oh)
{
    __shared__ float sh[256];
    int r = blockIdx.x, tid = threadIdx.x;
    const float* xr = xin + (size_t)r * C_DIM;
    float v[4]; float s = 0.f;
#pragma unroll
    for (int i = 0; i < 4; i++) { v[i] = xr[tid + 256 * i]; s += v[i]; }
    float mean = blk_sum(s, sh) * (1.0f / C_DIM);
    float d2 = 0.f;
#pragma unroll
    for (int i = 0; i < 4; i++) { float d = v[i] - mean; d2 += d * d; }
    float inv = rsqrtf(blk_sum(d2, sh) * (1.0f / C_DIM) + 1e-5f);
#pragma unroll
    for (int i = 0; i < 4; i++) {
        int c = tid + 256 * i;
        float y = (v[i] - mean) * inv * g[c] + b[c];
        size_t idx = (size_t)r * C_DIM + c;
        out[idx] = y;
        if (SPLIT) oh[idx] = __float2half_rn(y);
    }
}

// ================= fp16 1-pass HMMA GEMM, persistent CTAs ===================
// C[M,N] = A[M,K] * B[N,K]^T + bias (fp16 in, fp32 accum)
// OUT_MODE 0: fp32 out = gemm + bias + Xres (residual fused).
// OUT_MODE 1: gelu(.)->fp16. OUT_MODE 2: (.)*qscale->fp16 (QKV, Q in log2 dom).
#define GEMM_SMEM_BYTES (1024 + 3 * 32768)

template<int OUT_MODE>
__global__ __launch_bounds__(256, 2) void gemm_hmma1(
    const __half* __restrict__ Ah, const __half* __restrict__ Bh,
    const float* __restrict__ bias, const float* __restrict__ Xres,
    float* __restrict__ Cf, __half* __restrict__ Ch,
    int M, int N, int K)
{
    extern __shared__ char dsm[];
    const uint32_t smbase = (smem_to_u32(dsm) + 1023u) & ~1023u;
    const int tid = threadIdx.x;
    const int wid = tid >> 5;
    const int lid = tid & 31;
    const int warp_m = wid & 1;
    const int warp_n = wid >> 1;
    const int nchunk = K >> 6;
    const int ntx = N >> 7;
    const int ntiles = ntx * (M >> 7);
    const size_t rowbytes = (size_t)K * 2;

    const int lane15 = lid & 15;
    const int lanehi = lid >> 4;
    const int xr = lane15 & 7;
    const int lr = lid >> 2;
    const int lc = (lid & 3) * 2;

    for (int tile = blockIdx.x; tile < ntiles; tile += gridDim.x) {
        const int row0 = (tile / ntx) << 7;
        const int col0 = (tile % ntx) << 7;
        const char* gsrc[2] = {
            (const char*)(Ah + (size_t)row0 * K),
            (const char*)(Bh + (size_t)col0 * K) };

        auto load_chunk = [&](int c, int st) {
            const uint32_t sb = smbase + st * 32768;
            const size_t koff = (size_t)c * 128;
#pragma unroll
            for (int t = 0; t < 2; t++) {
#pragma unroll
                for (int j = 0; j < 4; j++) {
                    int u = tid + j * 256;
                    int r = u >> 3;
                    int cb = (u & 7) * 16;
                    const char* g = gsrc[t] + (size_t)r * rowbytes + koff + cb;
                    uint32_t sa = sb + t * 16384 + (uint32_t)(r * 128 + (cb ^ ((r & 7) << 4)));
                    CPA16(sa, g);
                }
            }
            asm volatile("cp.async.commit_group;");
        };

        float acc[4][4][4];
#pragma unroll
        for (int a = 0; a < 4; a++)
#pragma unroll
            for (int b = 0; b < 4; b++)
#pragma unroll
                for (int i = 0; i < 4; i++) acc[a][b][i] = 0.f;

        load_chunk(0, 0);
        load_chunk(1, 1);

        for (int c = 0; c < nchunk; c++) {
            if (c + 1 < nchunk) {
                asm volatile("cp.async.wait_group 1;");
            } else {
                asm volatile("cp.async.wait_group 0;");
            }
            __syncthreads();
            if (c + 2 < nchunk) load_chunk(c + 2, (c + 2) % 3);

            const uint32_t sb = smbase + (c % 3) * 32768;
            const uint32_t aBase = sb          + (uint32_t)(warp_m * 64 + lane15) * 128;
            const uint32_t bBase = sb + 16384  + (uint32_t)(warp_n * 32 + lane15) * 128;

#pragma unroll
            for (int ks = 0; ks < 4; ks++) {
                const uint32_t uoff = (uint32_t)(((ks * 2 + lanehi) ^ xr) * 16);
                uint32_t ah[4][4], bhv[2][4];
#pragma unroll
                for (int mt = 0; mt < 4; mt++)
                    ldsm4(ah[mt], aBase + mt * 2048 + uoff);
#pragma unroll
                for (int pt = 0; pt < 2; pt++)
                    ldsm4(bhv[pt], bBase + pt * 2048 + uoff);
#pragma unroll
                for (int mt = 0; mt < 4; mt++) {
#pragma unroll
                    for (int nt = 0; nt < 4; nt++) {
                        const int pt = nt >> 1, o = nt & 1;
                        mma16816(acc[mt][nt], ah[mt], bhv[pt][o], bhv[pt][o + 2]);
                    }
                }
            }
            __syncthreads();
        }

        // epilogue
#pragma unroll
        for (int mt = 0; mt < 4; mt++) {
            const int row = row0 + warp_m * 64 + mt * 16 + lr;
#pragma unroll
            for (int nt = 0; nt < 4; nt++) {
                const int col = col0 + warp_n * 32 + nt * 8 + lc;
                const float b0 = bias[col], b1 = bias[col + 1];
                float v0 = acc[mt][nt][0] + b0, v1 = acc[mt][nt][1] + b1;
                float v2 = acc[mt][nt][2] + b0, v3 = acc[mt][nt][3] + b1;
                if (OUT_MODE == 0) {
                    const size_t o0 = (size_t)row * N + col;
                    const size_t o1 = (size_t)(row + 8) * N + col;
                    float2 x0 = *(const float2*)(Xres + o0);
                    float2 x1 = *(const float2*)(Xres + o1);
                    float2 w0; w0.x = v0 + x0.x; w0.y = v1 + x0.y;
                    float2 w1; w1.x = v2 + x1.x; w1.y = v3 + x1.y;
                    *(float2*)(Cf + o0) = w0;
                    *(float2*)(Cf + o1) = w1;
                } else {
                    if (OUT_MODE == 1) {
                        v0 = 0.5f * v0 * (1.f + erff(v0 * 0.70710678118654752f));
                        v1 = 0.5f * v1 * (1.f + erff(v1 * 0.70710678118654752f));
                        v2 = 0.5f * v2 * (1.f + erff(v2 * 0.70710678118654752f));
                        v3 = 0.5f * v3 * (1.f + erff(v3 * 0.70710678118654752f));
                    } else {
                        float sc = (col < C_DIM) ? QSCALE : 1.0f;  // scale Q only
                        v0 *= sc; v1 *= sc; v2 *= sc; v3 *= sc;
                    }
                    __half2 hh0 = __floats2half2_rn(v0, v1);
                    __half2 hh1 = __floats2half2_rn(v2, v3);
                    *(__half2*)(Ch + (size_t)row * N + col) = hh0;
                    *(__half2*)(Ch + (size_t)(row + 8) * N + col) = hh1;
                }
            }
        }
    }
}

// ================= fp16 HMMA flash attention (sliding window) ===================
// Pure fp16, log2-domain softmax (Q pre-scaled by QSCALE). Mask loop only on
// boundary tiles (diagonal + window edge): ~3 of 17 tiles.
#define ATTN_SMEM (1024 + 3 * 8192)

__global__ __launch_bounds__(128, 4) void attn_mma_kernel(
    const __half* __restrict__ qkvh,
    const float* __restrict__ bqkv_l,
    __half* __restrict__ oh)
{
    extern __shared__ char dsm[];
    const uint32_t base = (smem_to_u32(dsm) + 1023u) & ~1023u;
    const uint32_t sQ = base;
    const uint32_t sK = base + 8192;
    const uint32_t sV = base + 16384;

    const int tid = threadIdx.x, wid = tid >> 5, lid = tid & 31;
    const int b = blockIdx.z, h = blockIdx.y, q0 = blockIdx.x * 64;
    const int lane15 = lid & 15, lanehi = lid >> 4, xr = lane15 & 7;
    const int tig = lid & 3, gid = lid >> 2;
    const size_t RS = 3 * C_DIM;

    // ---- Q tile: 64 rows x 128B ----
#pragma unroll
    for (int i = 0; i < 4; i++) {
        int u = tid + i * 128;
        int r = u >> 3, cu = u & 7;
        const char* g = (const char*)(qkvh + (size_t)(b * SEQ + q0 + r) * RS + h * HD) + cu * 16;
        CPA16(sQ + (uint32_t)(r * 128 + ((cu ^ (r & 7)) * 16)), g);
    }
    asm volatile("cp.async.commit_group;");
    asm volatile("cp.async.wait_group 0;");
    __syncthreads();

    uint32_t qf[4][4];
    {
        const uint32_t qrb = (uint32_t)((wid * 16 + lane15) * 128);
#pragma unroll
        for (int ks = 0; ks < 4; ks++) {
            const uint32_t uoff = (uint32_t)(((ks * 2 + lanehi) ^ xr) * 16);
            ldsm4(qf[ks], sQ + qrb + uoff);
        }
    }

    // ---- past zero-token init (log2 domain: q already scaled) ----
    const int tq0 = q0 + wid * 16 + gid, tq1 = tq0 + 8;
    const float* bk = bqkv_l + C_DIM + h * HD;
    const float* bv = bqkv_l + 2 * C_DIM + h * HD;
    float sp0 = 0.f, sp1 = 0.f;
    {
        const __half* q0p = qkvh + (size_t)(b * SEQ + tq0) * RS + h * HD + tig * 16;
        const __half* q1p = qkvh + (size_t)(b * SEQ + tq1) * RS + h * HD + tig * 16;
#pragma unroll
        for (int dd = 0; dd < 16; dd++) {
            float w = bk[tig * 16 + dd];
            sp0 += __half2float(q0p[dd]) * w;
            sp1 += __half2float(q1p[dd]) * w;
        }
        sp0 += __shfl_xor_sync(0xFFFFFFFF, sp0, 1); sp0 += __shfl_xor_sync(0xFFFFFFFF, sp0, 2);
        sp1 += __shfl_xor_sync(0xFFFFFFFF, sp1, 1); sp1 += __shfl_xor_sync(0xFFFFFFFF, sp1, 2);
    }
    const bool pv0 = (tq0 <= WIN - 1), pv1 = (tq1 <= WIN - 1);
    float m0 = pv0 ? sp0 : -1e30f, m1 = pv1 ? sp1 : -1e30f;
    float l0 = pv0 ? 1.f : 0.f,     l1 = pv1 ? 1.f : 0.f;
    float o[8][4];
#pragma unroll
    for (int nt = 0; nt < 8; nt++) {
        float bva = bv[nt * 8 + 2 * tig], bvb = bv[nt * 8 + 2 * tig + 1];
        o[nt][0] = pv0 ? bva : 0.f; o[nt][1] = pv0 ? bvb : 0.f;
        o[nt][2] = pv1 ? bva : 0.f; o[nt][3] = pv1 ? bvb : 0.f;
    }

    // ---- main loop over 64-key tiles ----
    const int jlo = (q0 > WIN) ? ((q0 - WIN) & ~63) : 0;
    for (int j0 = jlo; j0 < q0 + 64; j0 += 64) {
        __syncthreads();
#pragma unroll
        for (int i = 0; i < 8; i++) {
            int u = tid + i * 128;
            int t = u >> 9, idx = u & 511;
            int r = idx >> 3, cu = idx & 7;
            const size_t coloff = (size_t)C_DIM * (1 + t) + h * HD;
            const char* g = (const char*)(qkvh + (size_t)(b * SEQ + j0 + r) * RS + coloff) + cu * 16;
            CPA16(sK + (uint32_t)(t * 8192 + r * 128 + ((cu ^ (r & 7)) * 16)), g);
        }
        asm volatile("cp.async.commit_group;");
        asm volatile("cp.async.wait_group 0;");
        __syncthreads();

        // S = Q.K^T
        float s[8][4];
#pragma unroll
        for (int nt = 0; nt < 8; nt++)
#pragma unroll
            for (int i = 0; i < 4; i++) s[nt][i] = 0.f;
#pragma unroll
        for (int ks = 0; ks < 4; ks++) {
            const uint32_t uoff = (uint32_t)(((ks * 2 + lanehi) ^ xr) * 16);
            uint32_t kf[4][4];
#pragma unroll
            for (int pt = 0; pt < 4; pt++)
                ldsm4(kf[pt], sK + (uint32_t)((pt * 16 + lane15) * 128) + uoff);
#pragma unroll
            for (int nt = 0; nt < 8; nt++) {
                const int pt = nt >> 1, oo = nt & 1;
                mma16816(s[nt], qf[ks], kf[pt][oo], kf[pt][oo + 2]);
            }
        }
        // mask only on boundary tiles (uniform branch):
        // diagonal (j0 >= q0) or window-edge (j0 < q0-896)
        if (j0 >= q0 || j0 < q0 - 896) {
#pragma unroll
            for (int nt = 0; nt < 8; nt++)
#pragma unroll
                for (int i = 0; i < 4; i++) {
                    int key = j0 + nt * 8 + 2 * tig + (i & 1);
                    int tq = (i < 2) ? tq0 : tq1;
                    int dlt = tq - key;
                    if (dlt < 0 || dlt > WIN) s[nt][i] = -3.0e38f;
                }
        }
        // online softmax in log2 domain
        float mc0 = -3.0e38f, mc1 = -3.0e38f;
#pragma unroll
        for (int nt = 0; nt < 8; nt++) {
            mc0 = fmaxf(mc0, fmaxf(s[nt][0], s[nt][1]));
            mc1 = fmaxf(mc1, fmaxf(s[nt][2], s[nt][3]));
        }
        mc0 = fmaxf(mc0, __shfl_xor_sync(0xFFFFFFFF, mc0, 1));
        mc0 = fmaxf(mc0, __shfl_xor_sync(0xFFFFFFFF, mc0, 2));
        mc1 = fmaxf(mc1, __shfl_xor_sync(0xFFFFFFFF, mc1, 1));
        mc1 = fmaxf(mc1, __shfl_xor_sync(0xFFFFFFFF, mc1, 2));
        float mn0 = fmaxf(m0, mc0), mn1 = fmaxf(m1, mc1);
        float a0 = ex2f(m0 - mn0), a1 = ex2f(m1 - mn1);
        float rs0 = 0.f, rs1 = 0.f;
#pragma unroll
        for (int nt = 0; nt < 8; nt++) {
            s[nt][0] = ex2f(s[nt][0] - mn0); rs0 += s[nt][0];
            s[nt][1] = ex2f(s[nt][1] - mn0); rs0 += s[nt][1];
            s[nt][2] = ex2f(s[nt][2] - mn1); rs1 += s[nt][2];
            s[nt][3] = ex2f(s[nt][3] - mn1); rs1 += s[nt][3];
        }
        rs0 += __shfl_xor_sync(0xFFFFFFFF, rs0, 1); rs0 += __shfl_xor_sync(0xFFFFFFFF, rs0, 2);
        rs1 += __shfl_xor_sync(0xFFFFFFFF, rs1, 1); rs1 += __shfl_xor_sync(0xFFFFFFFF, rs1, 2);
        l0 = l0 * a0 + rs0; l1 = l1 * a1 + rs1;
        m0 = mn0; m1 = mn1;
#pragma unroll
        for (int nt = 0; nt < 8; nt++) {
            o[nt][0] *= a0; o[nt][1] *= a0; o[nt][2] *= a1; o[nt][3] *= a1;
        }
        // pack P -> fp16 A-frags
        uint32_t pa[4][4];
#pragma unroll
        for (int kt = 0; kt < 4; kt++) {
            pa[kt][0] = packh(s[2 * kt][0],     s[2 * kt][1]);
            pa[kt][1] = packh(s[2 * kt][2],     s[2 * kt][3]);
            pa[kt][2] = packh(s[2 * kt + 1][0], s[2 * kt + 1][1]);
            pa[kt][3] = packh(s[2 * kt + 1][2], s[2 * kt + 1][3]);
        }
        // O += P * V
#pragma unroll
        for (int kt = 0; kt < 4; kt++) {
            const uint32_t vrb = (uint32_t)((kt * 16 + lane15) * 128);
            uint32_t vf[4][4];
#pragma unroll
            for (int j = 0; j < 4; j++) {
                const uint32_t uo = (uint32_t)(((j * 2 + lanehi) ^ xr) * 16);
                ldsm4t(vf[j], sV + vrb + uo);
            }
#pragma unroll
            for (int j = 0; j < 4; j++) {
                mma16816(o[2 * j],     pa[kt], vf[j][0], vf[j][1]);
                mma16816(o[2 * j + 1], pa[kt], vf[j][2], vf[j][3]);
            }
        }
    }

    const float r0 = 1.f / l0, r1 = 1.f / l1;
#pragma unroll
    for (int nt = 0; nt < 8; nt++) {
        const int col = h * HD + nt * 8 + 2 * tig;
        __half2 hh0 = __floats2half2_rn(o[nt][0] * r0, o[nt][1] * r0);
        __half2 hh1 = __floats2half2_rn(o[nt][2] * r1, o[nt][3] * r1);
        *(__half2*)(oh + (size_t)(b * SEQ + tq0) * C_DIM + col) = hh0;
        *(__half2*)(oh + (size_t)(b * SEQ + tq1) * C_DIM + col) = hh1;
    }
}

// ================= launcher =================
extern "C" void kernel_launch(void* const* d_in, const int* in_sizes, int n_in,
                              void* d_out, int out_size)
{
    const float* x      = (const float*)d_in[0];
    const float* norm_g = (const float*)d_in[1];
    const float* norm_b = (const float*)d_in[2];
    const float* Wqkv   = (const float*)d_in[3];
    const float* bqkv   = (const float*)d_in[4];
    const float* Wo     = (const float*)d_in[5];
    const float* bo     = (const float*)d_in[6];
    const float* ln1_g  = (const float*)d_in[7];
    const float* ln1_b  = (const float*)d_in[8];
    const float* ln2_g  = (const float*)d_in[9];
    const float* ln2_b  = (const float*)d_in[10];
    const float* W1     = (const float*)d_in[11];
    const float* b1     = (const float*)d_in[12];
    const float* W2     = (const float*)d_in[13];
    const float* b2     = (const float*)d_in[14];
    float* out = (float*)d_out;

    float *gx, *gtmp;
    __half *gxh, *gah, *ghh, *gqh, *gwq, *gwo, *gw1, *gw2;
    cudaGetSymbolAddress((void**)&gx,   g_x);
    cudaGetSymbolAddress((void**)&gtmp, g_tmp);
    cudaGetSymbolAddress((void**)&gxh,  g_xh);
    cudaGetSymbolAddress((void**)&gah,  g_ah);
    cudaGetSymbolAddress((void**)&ghh,  g_hh);
    cudaGetSymbolAddress((void**)&gqh,  g_qkvh);
    cudaGetSymbolAddress((void**)&gwq,  g_wq);
    cudaGetSymbolAddress((void**)&gwo,  g_wo);
    cudaGetSymbolAddress((void**)&gw1,  g_w1);
    cudaGetSymbolAddress((void**)&gw2,  g_w2);

    cudaFuncSetAttribute(gemm_hmma1<0>, cudaFuncAttributeMaxDynamicSharedMemorySize, GEMM_SMEM_BYTES);
    cudaFuncSetAttribute(gemm_hmma1<1>, cudaFuncAttributeMaxDynamicSharedMemorySize, GEMM_SMEM_BYTES);
    cudaFuncSetAttribute(gemm_hmma1<2>, cudaFuncAttributeMaxDynamicSharedMemorySize, GEMM_SMEM_BYTES);
    cudaFuncSetAttribute(attn_mma_kernel, cudaFuncAttributeMaxDynamicSharedMemorySize, ATTN_SMEM);

    const int NQ = 3 * C_DIM * C_DIM;
    const int NO = C_DIM * C_DIM;
    const int N1 = HID_DIM * C_DIM;
    const int N2 = C_DIM * HID_DIM;

    auto gemm_grid = [](int M, int N) {
        int tiles = (M >> 7) * (N >> 7);
        return (tiles < NPERS) ? tiles : NPERS;
    };

    embed_ln_kernel<<<NROWS, 256>>>(x, norm_g, norm_b, gx, gxh);

    for (int l = 0; l < N_LAYERS; l++) {
        const float* bqkv_l = bqkv + (size_t)l * 3 * C_DIM;

        // cast all 4 weight matrices in one launch (attn stays ncu launch #4)
        cast4_kernel<<<1184, 256>>>(
            Wqkv + (size_t)l * NQ, gwq, NQ,
            Wo   + (size_t)l * NO, gwo, NO,
            W1   + (size_t)l * N1, gw1, N1,
            W2   + (size_t)l * N2, gw2, N2);

        // qkv = (x @ Wqkv^T + bqkv), Q scaled by QSCALE (log2 domain), fp16 out
        gemm_hmma1<2><<<gemm_grid(NROWS, 3 * C_DIM), 256, GEMM_SMEM_BYTES>>>(
            gxh, gwq, bqkv_l, nullptr, nullptr, gqh,
            NROWS, 3 * C_DIM, C_DIM);

        // pure-fp16 HMMA flash attention
        attn_mma_kernel<<<dim3(SEQ / 64, N_HEADS, BATCH), 128, ATTN_SMEM>>>(
            gqh, bqkv_l, gah);

        // tmp = x + attn @ Wo^T + bo   (residual fused)
        gemm_hmma1<0><<<gemm_grid(NROWS, C_DIM), 256, GEMM_SMEM_BYTES>>>(
            gah, gwo, bo + (size_t)l * C_DIM, gx, gtmp, nullptr,
            NROWS, C_DIM, C_DIM);

        // x = LN(tmp; ln1)
        ln_kernel<1><<<NROWS, 256>>>(gtmp, ln1_g + l * C_DIM, ln1_b + l * C_DIM, gx, gxh);

        // hid = gelu(x @ W1^T + b1) -> fp16
        gemm_hmma1<1><<<gemm_grid(NROWS, HID_DIM), 256, GEMM_SMEM_BYTES>>>(
            gxh, gw1, b1 + (size_t)l * HID_DIM, nullptr, nullptr, ghh,
            NROWS, HID_DIM, C_DIM);

        // tmp = x + hid @ W2^T + b2   (residual fused)
        gemm_hmma1<0><<<gemm_grid(NROWS, C_DIM), 256, GEMM_SMEM_BYTES>>>(
            ghh, gw2, b2 + (size_t)l * C_DIM, gx, gtmp, nullptr,
            NROWS, C_DIM, HID_DIM);

        // x = LN(tmp; ln2)
        if (l == N_LAYERS - 1)
            ln_kernel<0><<<NROWS, 256>>>(gtmp, ln2_g + l * C_DIM, ln2_b + l * C_DIM, out, nullptr);
        else
            ln_kernel<1><<<NROWS, 256>>>(gtmp, ln2_g + l * C_DIM, ln2_b + l * C_DIM, gx, gxh);
    }
}

// round 17
// speedup vs baseline: 1.0126x; 1.0069x over previous
#include <cuda_runtime.h>
#include <cuda_fp16.h>
#include <math.h>
#include <stdint.h>

#define C_DIM   1024
#define N_HEADS 16
#define HD      64
#define N_LAYERS 6
#define HID_DIM 4096
#define BATCH   2
#define SEQ     2048
#define NROWS   (BATCH*SEQ)
#define WIN     1000
#define NPERS   296     // 2 CTAs/SM x 148 SMs
// Q pre-scale: (1/sqrt(64)) * log2(e) -> softmax runs in log2 domain
#define QSCALE  0.18033688011112042f

// ================= scratch (no allocations allowed) =================
__device__ float g_x   [NROWS * C_DIM];
__device__ float g_tmp [NROWS * C_DIM];
__device__ __half g_xh[NROWS * C_DIM];
__device__ __half g_ah[NROWS * C_DIM];
__device__ __half g_hh[NROWS * HID_DIM];
__device__ __half g_qkvh[NROWS * 3 * C_DIM];
// per-layer fp16 weight buffers (dedicated per matrix)
__device__ __half g_wq[3 * C_DIM * C_DIM];
__device__ __half g_wo[C_DIM * C_DIM];
__device__ __half g_w1[HID_DIM * C_DIM];
__device__ __half g_w2[C_DIM * HID_DIM];

// ================= helpers =================
__device__ __forceinline__ uint32_t smem_to_u32(const void* p) {
    uint32_t a;
    asm("{ .reg .u64 t; cvta.to.shared.u64 t, %1; cvt.u32.u64 %0, t; }" : "=r"(a) : "l"(p));
    return a;
}
__device__ __forceinline__ float ex2f(float x) {
    float r;
    asm("ex2.approx.ftz.f32 %0, %1;" : "=f"(r) : "f"(x));
    return r;
}
__device__ __forceinline__ void ldsm4(uint32_t* r, uint32_t addr) {
    asm volatile("ldmatrix.sync.aligned.m8n8.x4.shared.b16 {%0,%1,%2,%3}, [%4];"
                 : "=r"(r[0]), "=r"(r[1]), "=r"(r[2]), "=r"(r[3]) : "r"(addr));
}
__device__ __forceinline__ void ldsm4t(uint32_t* r, uint32_t addr) {
    asm volatile("ldmatrix.sync.aligned.m8n8.x4.trans.shared.b16 {%0,%1,%2,%3}, [%4];"
                 : "=r"(r[0]), "=r"(r[1]), "=r"(r[2]), "=r"(r[3]) : "r"(addr));
}
__device__ __forceinline__ void mma16816(float* d, const uint32_t* a, uint32_t b0, uint32_t b1) {
    asm volatile("mma.sync.aligned.m16n8k16.row.col.f32.f16.f16.f32 "
                 "{%0,%1,%2,%3}, {%4,%5,%6,%7}, {%8,%9}, {%0,%1,%2,%3};"
                 : "+f"(d[0]), "+f"(d[1]), "+f"(d[2]), "+f"(d[3])
                 : "r"(a[0]), "r"(a[1]), "r"(a[2]), "r"(a[3]), "r"(b0), "r"(b1));
}
__device__ __forceinline__ uint32_t packh(float lo, float hi) {
    uint32_t r;
    asm("cvt.rn.f16x2.f32 %0, %1, %2;" : "=r"(r) : "f"(hi), "f"(lo));
    return r;
}
#define CPA16(dst, src) \
    asm volatile("cp.async.cg.shared.global [%0], [%1], 16;" :: "r"(dst), "l"(src))

// ================= 4-way weight cast kernel (fp32 -> fp16) =================
__global__ void cast4_kernel(
    const float* __restrict__ s0, __half* __restrict__ d0, int n0,
    const float* __restrict__ s1, __half* __restrict__ d1, int n1,
    const float* __restrict__ s2, __half* __restrict__ d2, int n2,
    const float* __restrict__ s3, __half* __restrict__ d3, int n3)
{
    int total = (n0 + n1 + n2 + n3) >> 1;
    for (int i = blockIdx.x * blockDim.x + threadIdx.x; i < total;
         i += gridDim.x * blockDim.x) {
        int j = i << 1;
        const float* s; __half* d;
        if (j < n0)              { s = s0; d = d0; }
        else if ((j -= n0) < n1) { s = s1; d = d1; }
        else if ((j -= n1) < n2) { s = s2; d = d2; }
        else                     { j -= n2; s = s3; d = d3; }
        float2 v = *(const float2*)(s + j);
        *(__half2*)(d + j) = __floats2half2_rn(v.x, v.y);
    }
}

// ================= block reduce =================
__device__ __forceinline__ float blk_sum(float v, float* sh) {
    int tid = threadIdx.x;
    sh[tid] = v; __syncthreads();
#pragma unroll
    for (int s = 128; s > 0; s >>= 1) { if (tid < s) sh[tid] += sh[tid + s]; __syncthreads(); }
    float r = sh[0]; __syncthreads();
    return r;
}

// ================= input LN + positional embedding =================
__global__ __launch_bounds__(256) void embed_ln_kernel(
    const float* __restrict__ x, const float* __restrict__ g, const float* __restrict__ b,
    float* __restrict__ out, __half* __restrict__ oh)
{
    __shared__ float sh[256];
    int r = blockIdx.x, t = r % SEQ, tid = threadIdx.x;
    const float* xr = x + (size_t)r * C_DIM;
    float v[4]; float s = 0.f;
#pragma unroll
    for (int i = 0; i < 4; i++) { v[i] = xr[tid + 256 * i]; s += v[i]; }
    float mean = blk_sum(s, sh) * (1.0f / C_DIM);
    float d2 = 0.f;
#pragma unroll
    for (int i = 0; i < 4; i++) { float d = v[i] - mean; d2 += d * d; }
    float inv = rsqrtf(blk_sum(d2, sh) * (1.0f / C_DIM) + 1e-5f);
    const float kln = 9.2103403719761836f / 511.0f;
    float tf = (float)t;
#pragma unroll
    for (int i = 0; i < 4; i++) {
        int c = tid + 256 * i;
        float ph = (c < 512) ? tf * expf(-((float)c) * kln) : tf * expf(-((float)(c - 512)) * kln);
        float pos = (c < 512) ? cosf(ph) : sinf(ph);
        float y = (v[i] - mean) * inv * g[c] + b[c] + pos;
        size_t idx = (size_t)r * C_DIM + c;
        out[idx] = y;
        oh[idx] = __float2half_rn(y);
    }
}

// ================= y = LN(in) (residual pre-added by GEMM epilogue) =========
template<int SPLIT>
__global__ __launch_bounds__(256) void ln_kernel(
    const float* __restrict__ xin,
    const float* __restrict__ g, const float* __restrict__ b,
    float* __restrict__ out, __half* __restrict__ oh)
{
    __shared__ float sh[256];
    int r = blockIdx.x, tid = threadIdx.x;
    const float* xr = xin + (size_t)r * C_DIM;
    float v[4]; float s = 0.f;
#pragma unroll
    for (int i = 0; i < 4; i++) { v[i] = xr[tid + 256 * i]; s += v[i]; }
    float mean = blk_sum(s, sh) * (1.0f / C_DIM);
    float d2 = 0.f;
#pragma unroll
    for (int i = 0; i < 4; i++) { float d = v[i] - mean; d2 += d * d; }
    float inv = rsqrtf(blk_sum(d2, sh) * (1.0f / C_DIM) + 1e-5f);
#pragma unroll
    for (int i = 0; i < 4; i++) {
        int c = tid + 256 * i;
        float y = (v[i] - mean) * inv * g[c] + b[c];
        size_t idx = (size_t)r * C_DIM + c;
        out[idx] = y;
        if (SPLIT) oh[idx] = __float2half_rn(y);
    }
}

// ================= fp16 1-pass HMMA GEMM, persistent CTAs ===================
// C[M,N] = A[M,K] * B[N,K]^T + bias (fp16 in, fp32 accum)
// Single-sync 3-stage multistage mainloop (one barrier per K-chunk).
// OUT_MODE 0: fp32 out = gemm + bias + Xres (residual fused).
// OUT_MODE 1: gelu(.)->fp16. OUT_MODE 2: (.)*qscale->fp16 (QKV, Q in log2 dom).
#define GEMM_SMEM_BYTES (1024 + 3 * 32768)

template<int OUT_MODE>
__global__ __launch_bounds__(256, 2) void gemm_hmma1(
    const __half* __restrict__ Ah, const __half* __restrict__ Bh,
    const float* __restrict__ bias, const float* __restrict__ Xres,
    float* __restrict__ Cf, __half* __restrict__ Ch,
    int M, int N, int K)
{
    extern __shared__ char dsm[];
    const uint32_t smbase = (smem_to_u32(dsm) + 1023u) & ~1023u;
    const int tid = threadIdx.x;
    const int wid = tid >> 5;
    const int lid = tid & 31;
    const int warp_m = wid & 1;
    const int warp_n = wid >> 1;
    const int nchunk = K >> 6;
    const int ntx = N >> 7;
    const int ntiles = ntx * (M >> 7);
    const size_t rowbytes = (size_t)K * 2;

    const int lane15 = lid & 15;
    const int lanehi = lid >> 4;
    const int xr = lane15 & 7;
    const int lr = lid >> 2;
    const int lc = (lid & 3) * 2;

    for (int tile = blockIdx.x; tile < ntiles; tile += gridDim.x) {
        const int row0 = (tile / ntx) << 7;
        const int col0 = (tile % ntx) << 7;
        const char* gsrc[2] = {
            (const char*)(Ah + (size_t)row0 * K),
            (const char*)(Bh + (size_t)col0 * K) };

        auto load_chunk = [&](int c, int st) {
            const uint32_t sb = smbase + st * 32768;
            const size_t koff = (size_t)c * 128;
#pragma unroll
            for (int t = 0; t < 2; t++) {
#pragma unroll
                for (int j = 0; j < 4; j++) {
                    int u = tid + j * 256;
                    int r = u >> 3;
                    int cb = (u & 7) * 16;
                    const char* g = gsrc[t] + (size_t)r * rowbytes + koff + cb;
                    uint32_t sa = sb + t * 16384 + (uint32_t)(r * 128 + (cb ^ ((r & 7) << 4)));
                    CPA16(sa, g);
                }
            }
            asm volatile("cp.async.commit_group;");
        };

        float acc[4][4][4];
#pragma unroll
        for (int a = 0; a < 4; a++)
#pragma unroll
            for (int b = 0; b < 4; b++)
#pragma unroll
                for (int i = 0; i < 4; i++) acc[a][b][i] = 0.f;

        load_chunk(0, 0);
        load_chunk(1, 1);

        for (int c = 0; c < nchunk; c++) {
            if (c + 1 < nchunk) {
                asm volatile("cp.async.wait_group 1;");
            } else {
                asm volatile("cp.async.wait_group 0;");
            }
            __syncthreads();
            // safe: every warp passing the barrier has finished compute(c-1),
            // and (c+2)%3 == (c-1)%3, so the prefetch cannot race readers.
            if (c + 2 < nchunk) load_chunk(c + 2, (c + 2) % 3);

            const uint32_t sb = smbase + (c % 3) * 32768;
            const uint32_t aBase = sb          + (uint32_t)(warp_m * 64 + lane15) * 128;
            const uint32_t bBase = sb + 16384  + (uint32_t)(warp_n * 32 + lane15) * 128;

#pragma unroll
            for (int ks = 0; ks < 4; ks++) {
                const uint32_t uoff = (uint32_t)(((ks * 2 + lanehi) ^ xr) * 16);
                uint32_t ah[4][4], bhv[2][4];
#pragma unroll
                for (int mt = 0; mt < 4; mt++)
                    ldsm4(ah[mt], aBase + mt * 2048 + uoff);
#pragma unroll
                for (int pt = 0; pt < 2; pt++)
                    ldsm4(bhv[pt], bBase + pt * 2048 + uoff);
#pragma unroll
                for (int mt = 0; mt < 4; mt++) {
#pragma unroll
                    for (int nt = 0; nt < 4; nt++) {
                        const int pt = nt >> 1, o = nt & 1;
                        mma16816(acc[mt][nt], ah[mt], bhv[pt][o], bhv[pt][o + 2]);
                    }
                }
            }
            // no trailing barrier (single-sync multistage)
        }

        // epilogue (acc registers only; smem reuse protected by next tile's sync)
        __syncthreads();
#pragma unroll
        for (int mt = 0; mt < 4; mt++) {
            const int row = row0 + warp_m * 64 + mt * 16 + lr;
#pragma unroll
            for (int nt = 0; nt < 4; nt++) {
                const int col = col0 + warp_n * 32 + nt * 8 + lc;
                const float b0 = bias[col], b1 = bias[col + 1];
                float v0 = acc[mt][nt][0] + b0, v1 = acc[mt][nt][1] + b1;
                float v2 = acc[mt][nt][2] + b0, v3 = acc[mt][nt][3] + b1;
                if (OUT_MODE == 0) {
                    const size_t o0 = (size_t)row * N + col;
                    const size_t o1 = (size_t)(row + 8) * N + col;
                    float2 x0 = *(const float2*)(Xres + o0);
                    float2 x1 = *(const float2*)(Xres + o1);
                    float2 w0; w0.x = v0 + x0.x; w0.y = v1 + x0.y;
                    float2 w1; w1.x = v2 + x1.x; w1.y = v3 + x1.y;
                    *(float2*)(Cf + o0) = w0;
                    *(float2*)(Cf + o1) = w1;
                } else {
                    if (OUT_MODE == 1) {
                        v0 = 0.5f * v0 * (1.f + erff(v0 * 0.70710678118654752f));
                        v1 = 0.5f * v1 * (1.f + erff(v1 * 0.70710678118654752f));
                        v2 = 0.5f * v2 * (1.f + erff(v2 * 0.70710678118654752f));
                        v3 = 0.5f * v3 * (1.f + erff(v3 * 0.70710678118654752f));
                    } else {
                        float sc = (col < C_DIM) ? QSCALE : 1.0f;  // scale Q only
                        v0 *= sc; v1 *= sc; v2 *= sc; v3 *= sc;
                    }
                    __half2 hh0 = __floats2half2_rn(v0, v1);
                    __half2 hh1 = __floats2half2_rn(v2, v3);
                    *(__half2*)(Ch + (size_t)row * N + col) = hh0;
                    *(__half2*)(Ch + (size_t)(row + 8) * N + col) = hh1;
                }
            }
        }
    }
}

// ================= fp16 HMMA flash attention (sliding window) ===================
// Pure fp16, log2-domain softmax, double-buffered K/V with cp.async prefetch:
// one barrier per key tile, next tile loads overlap current tile compute.
#define ATTN_SMEM (1024 + 8192 + 2 * 16384)

__global__ __launch_bounds__(128, 4) void attn_mma_kernel(
    const __half* __restrict__ qkvh,
    const float* __restrict__ bqkv_l,
    __half* __restrict__ oh)
{
    extern __shared__ char dsm[];
    const uint32_t base = (smem_to_u32(dsm) + 1023u) & ~1023u;
    const uint32_t sQ = base;
    const uint32_t sKV = base + 8192;      // stage st: K at +st*16384, V at +8192

    const int tid = threadIdx.x, wid = tid >> 5, lid = tid & 31;
    const int b = blockIdx.z, h = blockIdx.y, q0 = blockIdx.x * 64;
    const int lane15 = lid & 15, lanehi = lid >> 4, xr = lane15 & 7;
    const int tig = lid & 3, gid = lid >> 2;
    const size_t RS = 3 * C_DIM;

    auto load_tile = [&](int j0, int st) {
        const uint32_t sb = sKV + st * 16384;
#pragma unroll
        for (int i = 0; i < 8; i++) {
            int u = tid + i * 128;       // 0..1023
            int t = u >> 9, idx = u & 511;
            int r = idx >> 3, cu = idx & 7;
            const size_t coloff = (size_t)C_DIM * (1 + t) + h * HD;
            const char* g = (const char*)(qkvh + (size_t)(b * SEQ + j0 + r) * RS + coloff) + cu * 16;
            CPA16(sb + (uint32_t)(t * 8192 + r * 128 + ((cu ^ (r & 7)) * 16)), g);
        }
        asm volatile("cp.async.commit_group;");
    };

    // ---- Q tile: 64 rows x 128B (group 0), then prefetch first K/V tile ----
#pragma unroll
    for (int i = 0; i < 4; i++) {
        int u = tid + i * 128;
        int r = u >> 3, cu = u & 7;
        const char* g = (const char*)(qkvh + (size_t)(b * SEQ + q0 + r) * RS + h * HD) + cu * 16;
        CPA16(sQ + (uint32_t)(r * 128 + ((cu ^ (r & 7)) * 16)), g);
    }
    asm volatile("cp.async.commit_group;");
    const int jlo = (q0 > WIN) ? ((q0 - WIN) & ~63) : 0;
    load_tile(jlo, 0);
    asm volatile("cp.async.wait_group 1;");   // Q ready (tile0 may be in flight)
    __syncthreads();

    uint32_t qf[4][4];
    {
        const uint32_t qrb = (uint32_t)((wid * 16 + lane15) * 128);
#pragma unroll
        for (int ks = 0; ks < 4; ks++) {
            const uint32_t uoff = (uint32_t)(((ks * 2 + lanehi) ^ xr) * 16);
            ldsm4(qf[ks], sQ + qrb + uoff);
        }
    }

    // ---- past zero-token init (log2 domain: q already scaled) ----
    const int tq0 = q0 + wid * 16 + gid, tq1 = tq0 + 8;
    const float* bk = bqkv_l + C_DIM + h * HD;
    const float* bv = bqkv_l + 2 * C_DIM + h * HD;
    float sp0 = 0.f, sp1 = 0.f;
    {
        const __half* q0p = qkvh + (size_t)(b * SEQ + tq0) * RS + h * HD + tig * 16;
        const __half* q1p = qkvh + (size_t)(b * SEQ + tq1) * RS + h * HD + tig * 16;
#pragma unroll
        for (int dd = 0; dd < 16; dd++) {
            float w = bk[tig * 16 + dd];
            sp0 += __half2float(q0p[dd]) * w;
            sp1 += __half2float(q1p[dd]) * w;
        }
        sp0 += __shfl_xor_sync(0xFFFFFFFF, sp0, 1); sp0 += __shfl_xor_sync(0xFFFFFFFF, sp0, 2);
        sp1 += __shfl_xor_sync(0xFFFFFFFF, sp1, 1); sp1 += __shfl_xor_sync(0xFFFFFFFF, sp1, 2);
    }
    const bool pv0 = (tq0 <= WIN - 1), pv1 = (tq1 <= WIN - 1);
    float m0 = pv0 ? sp0 : -1e30f, m1 = pv1 ? sp1 : -1e30f;
    float l0 = pv0 ? 1.f : 0.f,     l1 = pv1 ? 1.f : 0.f;
    float o[8][4];
#pragma unroll
    for (int nt = 0; nt < 8; nt++) {
        float bva = bv[nt * 8 + 2 * tig], bvb = bv[nt * 8 + 2 * tig + 1];
        o[nt][0] = pv0 ? bva : 0.f; o[nt][1] = pv0 ? bvb : 0.f;
        o[nt][2] = pv1 ? bva : 0.f; o[nt][3] = pv1 ? bvb : 0.f;
    }

    // ---- main loop over 64-key tiles (pipelined) ----
    int st = 0;
    for (int j0 = jlo; j0 < q0 + 64; j0 += 64, st ^= 1) {
        asm volatile("cp.async.wait_group 0;");   // current tile ready
        __syncthreads();
        if (j0 < q0) load_tile(j0 + 64, st ^ 1);  // overlap next loads with compute

        const uint32_t sK = sKV + st * 16384;
        const uint32_t sV = sK + 8192;

        // S = Q.K^T
        float s[8][4];
#pragma unroll
        for (int nt = 0; nt < 8; nt++)
#pragma unroll
            for (int i = 0; i < 4; i++) s[nt][i] = 0.f;
#pragma unroll
        for (int ks = 0; ks < 4; ks++) {
            const uint32_t uoff = (uint32_t)(((ks * 2 + lanehi) ^ xr) * 16);
            uint32_t kf[4][4];
#pragma unroll
            for (int pt = 0; pt < 4; pt++)
                ldsm4(kf[pt], sK + (uint32_t)((pt * 16 + lane15) * 128) + uoff);
#pragma unroll
            for (int nt = 0; nt < 8; nt++) {
                const int pt = nt >> 1, oo = nt & 1;
                mma16816(s[nt], qf[ks], kf[pt][oo], kf[pt][oo + 2]);
            }
        }
        // mask only on boundary tiles (uniform branch)
        if (j0 >= q0 || j0 < q0 - 896) {
#pragma unroll
            for (int nt = 0; nt < 8; nt++)
#pragma unroll
                for (int i = 0; i < 4; i++) {
                    int key = j0 + nt * 8 + 2 * tig + (i & 1);
                    int tq = (i < 2) ? tq0 : tq1;
                    int dlt = tq - key;
                    if (dlt < 0 || dlt > WIN) s[nt][i] = -3.0e38f;
                }
        }
        // online softmax in log2 domain
        float mc0 = -3.0e38f, mc1 = -3.0e38f;
#pragma unroll
        for (int nt = 0; nt < 8; nt++) {
            mc0 = fmaxf(mc0, fmaxf(s[nt][0], s[nt][1]));
            mc1 = fmaxf(mc1, fmaxf(s[nt][2], s[nt][3]));
        }
        mc0 = fmaxf(mc0, __shfl_xor_sync(0xFFFFFFFF, mc0, 1));
        mc0 = fmaxf(mc0, __shfl_xor_sync(0xFFFFFFFF, mc0, 2));
        mc1 = fmaxf(mc1, __shfl_xor_sync(0xFFFFFFFF, mc1, 1));
        mc1 = fmaxf(mc1, __shfl_xor_sync(0xFFFFFFFF, mc1, 2));
        float mn0 = fmaxf(m0, mc0), mn1 = fmaxf(m1, mc1);
        float a0 = ex2f(m0 - mn0), a1 = ex2f(m1 - mn1);
        float rs0 = 0.f, rs1 = 0.f;
#pragma unroll
        for (int nt = 0; nt < 8; nt++) {
            s[nt][0] = ex2f(s[nt][0] - mn0); rs0 += s[nt][0];
            s[nt][1] = ex2f(s[nt][1] - mn0); rs0 += s[nt][1];
            s[nt][2] = ex2f(s[nt][2] - mn1); rs1 += s[nt][2];
            s[nt][3] = ex2f(s[nt][3] - mn1); rs1 += s[nt][3];
        }
        rs0 += __shfl_xor_sync(0xFFFFFFFF, rs0, 1); rs0 += __shfl_xor_sync(0xFFFFFFFF, rs0, 2);
        rs1 += __shfl_xor_sync(0xFFFFFFFF, rs1, 1); rs1 += __shfl_xor_sync(0xFFFFFFFF, rs1, 2);
        l0 = l0 * a0 + rs0; l1 = l1 * a1 + rs1;
        m0 = mn0; m1 = mn1;
#pragma unroll
        for (int nt = 0; nt < 8; nt++) {
            o[nt][0] *= a0; o[nt][1] *= a0; o[nt][2] *= a1; o[nt][3] *= a1;
        }
        // pack P -> fp16 A-frags
        uint32_t pa[4][4];
#pragma unroll
        for (int kt = 0; kt < 4; kt++) {
            pa[kt][0] = packh(s[2 * kt][0],     s[2 * kt][1]);
            pa[kt][1] = packh(s[2 * kt][2],     s[2 * kt][3]);
            pa[kt][2] = packh(s[2 * kt + 1][0], s[2 * kt + 1][1]);
            pa[kt][3] = packh(s[2 * kt + 1][2], s[2 * kt + 1][3]);
        }
        // O += P * V
#pragma unroll
        for (int kt = 0; kt < 4; kt++) {
            const uint32_t vrb = (uint32_t)((kt * 16 + lane15) * 128);
            uint32_t vf[4][4];
#pragma unroll
            for (int j = 0; j < 4; j++) {
                const uint32_t uo = (uint32_t)(((j * 2 + lanehi) ^ xr) * 16);
                ldsm4t(vf[j], sV + vrb + uo);
            }
#pragma unroll
            for (int j = 0; j < 4; j++) {
                mma16816(o[2 * j],     pa[kt], vf[j][0], vf[j][1]);
                mma16816(o[2 * j + 1], pa[kt], vf[j][2], vf[j][3]);
            }
        }
    }

    const float r0 = 1.f / l0, r1 = 1.f / l1;
#pragma unroll
    for (int nt = 0; nt < 8; nt++) {
        const int col = h * HD + nt * 8 + 2 * tig;
        __half2 hh0 = __floats2half2_rn(o[nt][0] * r0, o[nt][1] * r0);
        __half2 hh1 = __floats2half2_rn(o[nt][2] * r1, o[nt][3] * r1);
        *(__half2*)(oh + (size_t)(b * SEQ + tq0) * C_DIM + col) = hh0;
        *(__half2*)(oh + (size_t)(b * SEQ + tq1) * C_DIM + col) = hh1;
    }
}

// ================= launcher =================
extern "C" void kernel_launch(void* const* d_in, const int* in_sizes, int n_in,
                              void* d_out, int out_size)
{
    const float* x      = (const float*)d_in[0];
    const float* norm_g = (const float*)d_in[1];
    const float* norm_b = (const float*)d_in[2];
    const float* Wqkv   = (const float*)d_in[3];
    const float* bqkv   = (const float*)d_in[4];
    const float* Wo     = (const float*)d_in[5];
    const float* bo     = (const float*)d_in[6];
    const float* ln1_g  = (const float*)d_in[7];
    const float* ln1_b  = (const float*)d_in[8];
    const float* ln2_g  = (const float*)d_in[9];
    const float* ln2_b  = (const float*)d_in[10];
    const float* W1     = (const float*)d_in[11];
    const float* b1     = (const float*)d_in[12];
    const float* W2     = (const float*)d_in[13];
    const float* b2     = (const float*)d_in[14];
    float* out = (float*)d_out;

    float *gx, *gtmp;
    __half *gxh, *gah, *ghh, *gqh, *gwq, *gwo, *gw1, *gw2;
    cudaGetSymbolAddress((void**)&gx,   g_x);
    cudaGetSymbolAddress((void**)&gtmp, g_tmp);
    cudaGetSymbolAddress((void**)&gxh,  g_xh);
    cudaGetSymbolAddress((void**)&gah,  g_ah);
    cudaGetSymbolAddress((void**)&ghh,  g_hh);
    cudaGetSymbolAddress((void**)&gqh,  g_qkvh);
    cudaGetSymbolAddress((void**)&gwq,  g_wq);
    cudaGetSymbolAddress((void**)&gwo,  g_wo);
    cudaGetSymbolAddress((void**)&gw1,  g_w1);
    cudaGetSymbolAddress((void**)&gw2,  g_w2);

    cudaFuncSetAttribute(gemm_hmma1<0>, cudaFuncAttributeMaxDynamicSharedMemorySize, GEMM_SMEM_BYTES);
    cudaFuncSetAttribute(gemm_hmma1<1>, cudaFuncAttributeMaxDynamicSharedMemorySize, GEMM_SMEM_BYTES);
    cudaFuncSetAttribute(gemm_hmma1<2>, cudaFuncAttributeMaxDynamicSharedMemorySize, GEMM_SMEM_BYTES);
    cudaFuncSetAttribute(attn_mma_kernel, cudaFuncAttributeMaxDynamicSharedMemorySize, ATTN_SMEM);

    const int NQ = 3 * C_DIM * C_DIM;
    const int NO = C_DIM * C_DIM;
    const int N1 = HID_DIM * C_DIM;
    const int N2 = C_DIM * HID_DIM;

    auto gemm_grid = [](int M, int N) {
        int tiles = (M >> 7) * (N >> 7);
        return (tiles < NPERS) ? tiles : NPERS;
    };

    embed_ln_kernel<<<NROWS, 256>>>(x, norm_g, norm_b, gx, gxh);

    for (int l = 0; l < N_LAYERS; l++) {
        const float* bqkv_l = bqkv + (size_t)l * 3 * C_DIM;

        // cast all 4 weight matrices in one launch (attn stays ncu launch #4)
        cast4_kernel<<<1184, 256>>>(
            Wqkv + (size_t)l * NQ, gwq, NQ,
            Wo   + (size_t)l * NO, gwo, NO,
            W1   + (size_t)l * N1, gw1, N1,
            W2   + (size_t)l * N2, gw2, N2);

        // qkv = (x @ Wqkv^T + bqkv), Q scaled by QSCALE (log2 domain), fp16 out
        gemm_hmma1<2><<<gemm_grid(NROWS, 3 * C_DIM), 256, GEMM_SMEM_BYTES>>>(
            gxh, gwq, bqkv_l, nullptr, nullptr, gqh,
            NROWS, 3 * C_DIM, C_DIM);

        // pure-fp16 HMMA flash attention
        attn_mma_kernel<<<dim3(SEQ / 64, N_HEADS, BATCH), 128, ATTN_SMEM>>>(
            gqh, bqkv_l, gah);

        // tmp = x + attn @ Wo^T + bo   (residual fused)
        gemm_hmma1<0><<<gemm_grid(NROWS, C_DIM), 256, GEMM_SMEM_BYTES>>>(
            gah, gwo, bo + (size_t)l * C_DIM, gx, gtmp, nullptr,
            NROWS, C_DIM, C_DIM);

        // x = LN(tmp; ln1)
        ln_kernel<1><<<NROWS, 256>>>(gtmp, ln1_g + l * C_DIM, ln1_b + l * C_DIM, gx, gxh);

        // hid = gelu(x @ W1^T + b1) -> fp16
        gemm_hmma1<1><<<gemm_grid(NROWS, HID_DIM), 256, GEMM_SMEM_BYTES>>>(
            gxh, gw1, b1 + (size_t)l * HID_DIM, nullptr, nullptr, ghh,
            NROWS, HID_DIM, C_DIM);

        // tmp = x + hid @ W2^T + b2   (residual fused)
        gemm_hmma1<0><<<gemm_grid(NROWS, C_DIM), 256, GEMM_SMEM_BYTES>>>(
            ghh, gw2, b2 + (size_t)l * C_DIM, gx, gtmp, nullptr,
            NROWS, C_DIM, HID_DIM);

        // x = LN(tmp; ln2)
        if (l == N_LAYERS - 1)
            ln_kernel<0><<<NROWS, 256>>>(gtmp, ln2_g + l * C_DIM, ln2_b + l * C_DIM, out, nullptr);
        else
            ln_kernel<1><<<NROWS, 256>>>(gtmp, ln2_g + l * C_DIM, ln2_b + l * C_DIM, gx, gxh);
    }
}